// round 9
// baseline (speedup 1.0000x reference)
#include <cuda_runtime.h>
#include <math.h>

#define BB   16384
#define EE   8
#define CC   1000
#define DD   59
#define HH1  256
#define HH2  128
#define FEPS 1e-8f
#define LNEPS 1e-5f
#define LN2F 0.69314718055994530942f

// ---------------------------------------------------------------------------
__device__ __forceinline__ void cp_async16(void* smem_ptr, const void* gmem) {
    unsigned s = (unsigned)__cvta_generic_to_shared(smem_ptr);
    asm volatile("cp.async.cg.shared.global [%0], [%1], 16;\n" :: "r"(s), "l"(gmem));
}
#define CP_COMMIT() asm volatile("cp.async.commit_group;\n" ::: "memory")
#define CP_WAIT0()  asm volatile("cp.async.wait_group 0;\n" ::: "memory")

// ---------------------------------------------------------------------------
// Kernel A: feature extraction. 256 thr/block, 4 blocks/SM.
// Phase 1 reads each expert float4 ONCE into registers (8 LDS.128, not 24).
// dyn smem: buf[8000] + sdtv[2048] + spl[2048] = 48384 B
// ---------------------------------------------------------------------------
__global__ void __launch_bounds__(256, 4) feat_kernel(const float* __restrict__ P,
                                                      float* __restrict__ feats)
{
    extern __shared__ float dyn[];
    float* buf  = dyn;             // 8000
    float* sdtv = dyn + 8000;      // 8*256
    float* spl  = sdtv + 8*256;    // 8*256

    __shared__ float s_feat[64];
    __shared__ float s_sq[EE];
    __shared__ float s_red[16];
    __shared__ float s_ge2, s_gent;

    const int tid  = threadIdx.x;
    const int lane = tid & 31;
    const int wid  = tid >> 5;

    for (int b = blockIdx.x; b < BB; b += gridDim.x) {
        // ---- stage item into smem ----
        {
            const float4* src = reinterpret_cast<const float4*>(P + (size_t)b*(EE*CC));
            float4* dst = reinterpret_cast<float4*>(buf);
            for (int i = tid; i < EE*CC/4; i += 256) cp_async16(&dst[i], &src[i]);
        }
        CP_COMMIT();
        CP_WAIT0();
        __syncthreads();

        // ---- phase 1: single-read of 8 expert float4s; mean/L/dtv/pl ----
        float ge2 = 0.f, gent = 0.f;
        if (tid < CC/4) {
            const float4* pb = reinterpret_cast<const float4*>(buf);
            float4 pv[EE];
            #pragma unroll
            for (int e = 0; e < EE; e++) pv[e] = pb[e*(CC/4) + tid];
            float4 m = pv[0];
            #pragma unroll
            for (int e = 1; e < EE; e++) {
                m.x += pv[e].x; m.y += pv[e].y; m.z += pv[e].z; m.w += pv[e].w;
            }
            m.x *= 0.125f; m.y *= 0.125f; m.z *= 0.125f; m.w *= 0.125f;
            float4 L;
            L.x = __log2f(m.x + FEPS);
            L.y = __log2f(m.y + FEPS);
            L.z = __log2f(m.z + FEPS);
            L.w = __log2f(m.w + FEPS);
            ge2  = m.x*m.x + m.y*m.y + m.z*m.z + m.w*m.w;
            gent = m.x*L.x + m.y*L.y + m.z*L.z + m.w*L.w;
            #pragma unroll
            for (int e = 0; e < EE; e++) {
                sdtv[e*256 + tid] = pv[e].x*m.x + pv[e].y*m.y + pv[e].z*m.z + pv[e].w*m.w;
                spl [e*256 + tid] = pv[e].x*L.x + pv[e].y*L.y + pv[e].z*L.z + pv[e].w*L.w;
            }
        } else {
            #pragma unroll
            for (int e = 0; e < EE; e++) {
                sdtv[e*256 + tid] = 0.f;
                spl [e*256 + tid] = 0.f;
            }
        }
        #pragma unroll
        for (int off = 16; off; off >>= 1) {
            ge2  += __shfl_xor_sync(0xffffffffu, ge2,  off);
            gent += __shfl_xor_sync(0xffffffffu, gent, off);
        }
        if (lane == 0) { s_red[wid] = ge2; s_red[8 + wid] = gent; }
        __syncthreads();
        if (tid == 0) {
            float a = 0.f, g = 0.f;
            #pragma unroll
            for (int w = 0; w < 8; w++) { a += s_red[w]; g += s_red[8 + w]; }
            s_ge2 = a; s_gent = g;
        }
        __syncthreads();

        // ---- phase 2: warp wid handles expert wid ----
        {
            const float mn = fmaxf(sqrtf(s_ge2), FEPS);
            const float4* row = reinterpret_cast<const float4*>(buf) + wid*(CC/4);

            float slp = 0.f, sq = 0.f;
            float v0 = 0.f, v1 = 0.f, v2 = 0.f, v3 = 0.f, v4 = 0.f;

            #pragma unroll
            for (int k = 0; k < 8; k++) {
                int t = lane + 32*k;
                if (t < CC/4) {
                    float4 p = row[t];
                    #define DOELEM(px)                                           \
                    {                                                            \
                        float lp = __log2f((px) + FEPS);                         \
                        slp += (px)*lp;                                          \
                        sq  += (px)*(px);                                        \
                        float t0 = fminf(v0, (px)); v0 = fmaxf(v0, (px));        \
                        float t1 = fminf(v1, t0);   v1 = fmaxf(v1, t0);          \
                        float t2 = fminf(v2, t1);   v2 = fmaxf(v2, t1);          \
                        float t3 = fminf(v3, t2);   v3 = fmaxf(v3, t2);          \
                        v4 = fmaxf(v4, t3);                                      \
                    }
                    DOELEM(p.x) DOELEM(p.y) DOELEM(p.z) DOELEM(p.w)
                    #undef DOELEM
                }
            }
            #pragma unroll
            for (int off = 16; off; off >>= 1) {
                slp += __shfl_xor_sync(0xffffffffu, slp, off);
                sq  += __shfl_xor_sync(0xffffffffu, sq,  off);
            }

            float dtv, pl;
            {
                const float4* dp = reinterpret_cast<const float4*>(sdtv + wid*256);
                const float4* lp = reinterpret_cast<const float4*>(spl  + wid*256);
                float4 a = dp[lane], b4 = dp[lane + 32];
                float4 c = lp[lane], d4 = lp[lane + 32];
                float sd = a.x+a.y+a.z+a.w + b4.x+b4.y+b4.z+b4.w;
                float sl = c.x+c.y+c.z+c.w + d4.x+d4.y+d4.z+d4.w;
                #pragma unroll
                for (int off = 16; off; off >>= 1) {
                    sd += __shfl_xor_sync(0xffffffffu, sd, off);
                    sl += __shfl_xor_sync(0xffffffffu, sl, off);
                }
                dtv = sd; pl = sl;
            }

            float o0, o1, o2, o3, o4;
            #pragma unroll
            for (int r = 0; r < 5; r++) {
                unsigned myb = __float_as_uint(v0);
                unsigned mxb = __reduce_max_sync(0xffffffffu, myb);
                unsigned msk = __ballot_sync(0xffffffffu, myb == mxb);
                if (lane == __ffs(msk) - 1) { v0 = v1; v1 = v2; v2 = v3; v3 = v4; v4 = 0.f; }
                float mx = __uint_as_float(mxb);
                if (r == 0) o0 = mx; else if (r == 1) o1 = mx;
                else if (r == 2) o2 = mx; else if (r == 3) o3 = mx; else o4 = mx;
            }

            if (lane == 0) {
                float ent  = -slp * LN2F;
                float mass = o0 + o1 + o2 + o3 + o4;
                float pn   = fmaxf(sqrtf(sq), FEPS);
                s_feat[0*EE + wid] = ent;
                s_feat[1*EE + wid] = mass;
                s_feat[2*EE + wid] = 1.f - mass;
                s_feat[3*EE + wid] = o0;
                s_feat[4*EE + wid] = o0 - o1;
                s_feat[5*EE + wid] = dtv / (pn * mn);
                s_feat[6*EE + wid] = (slp - pl) * LN2F;
                s_sq[wid] = sq;
            }
        }
        __syncthreads();

        if (tid == 0) {
            float totsq = 0.f;
            #pragma unroll
            for (int e = 0; e < EE; e++) totsq += s_sq[e];
            float mcv = (totsq - 8.f * s_ge2) * (1.f / 7000.f);
            float mu = 0.f;
            #pragma unroll
            for (int e = 0; e < EE; e++) mu += s_feat[3*EE + e];
            mu *= 0.125f;
            float var = 0.f;
            #pragma unroll
            for (int e = 0; e < EE; e++) {
                float d = s_feat[3*EE + e] - mu;
                var += d * d;
            }
            s_feat[56] = -s_gent * LN2F;
            s_feat[57] = mcv;
            s_feat[58] = sqrtf(var * (1.f/7.f));
        }
        __syncthreads();

        if (tid < DD) {
            float v = s_feat[tid];
            v = fminf(fmaxf(v, -100.f), 100.f);
            feats[(size_t)b * DD + tid] = v;
        }
        __syncthreads();
    }
}

// ---------------------------------------------------------------------------
// Kernel B: MLP, 4x4 register tiles, 32 rows per chunk, 512 threads.
// W1/W2 via LDG.128 (L1/L2 resident). smem ~66KB -> 2 blocks/SM.
// ---------------------------------------------------------------------------
#define RPC 32

__global__ void __launch_bounds__(512, 2) mlp_kernel(
    const float* __restrict__ feats,
    const float* __restrict__ W1, const float* __restrict__ b1,
    const float* __restrict__ g1, const float* __restrict__ be1,
    const float* __restrict__ W2, const float* __restrict__ b2,
    const float* __restrict__ g2, const float* __restrict__ be2,
    const float* __restrict__ W3, const float* __restrict__ b3,
    float* __restrict__ wout, float* __restrict__ lout)
{
    extern __shared__ float sm[];
    float* sf   = sm;                  // 32*60 = 1920
    float* sh1  = sf   + RPC*60;       // 32*256 = 8192
    float* sh2  = sh1  + RPC*HH1;      // 32*128 = 4096
    float* sW3  = sh2  + RPC*HH2;      // 128*8 = 1024
    float* sb1  = sW3  + HH2*EE;       // 256
    float* sg1  = sb1  + HH1;          // 256
    float* sbe1 = sg1  + HH1;          // 256
    float* sb2  = sbe1 + HH1;          // 128
    float* sg2  = sb2  + HH2;          // 128
    float* sbe2 = sg2  + HH2;          // 128
    float* sb3  = sbe2 + HH2;          // 8
    float* sred = sb3  + EE;           // 16 warps * 8 = 128

    const int tid  = threadIdx.x;
    const int lane = tid & 31;
    const int wid  = tid >> 5;

    for (int i = tid; i < HH2*EE; i += 512) sW3[i] = W3[i];
    for (int i = tid; i < HH1;    i += 512) { sb1[i] = b1[i]; sg1[i] = g1[i]; sbe1[i] = be1[i]; }
    for (int i = tid; i < HH2;    i += 512) { sb2[i] = b2[i]; sg2[i] = g2[i]; sbe2[i] = be2[i]; }
    if (tid < EE) sb3[tid] = b3[tid];
    __syncthreads();

    const int nchunks = BB / RPC;   // 512
    for (int chunk = blockIdx.x; chunk < nchunks; chunk += gridDim.x) {
        const int row0 = chunk * RPC;

        // ---- stage feats (stride-60 rows) ----
        for (int t = tid; t < RPC*DD; t += 512) {
            int r = t / DD;
            int i = t - r*DD;
            sf[r*60 + i] = feats[(size_t)row0 * DD + t];
        }
        __syncthreads();

        // ---- layer 1: 59 -> 256. 4 cols x 4 rows per thread ----
        {
            const int q   = tid & 63;          // col quad: cols 4q..4q+3
            const int rg  = tid >> 6;          // 8 rowgroups x 4 rows
            float acc[4][4];
            #pragma unroll
            for (int r = 0; r < 4; r++)
                #pragma unroll
                for (int c = 0; c < 4; c++) acc[r][c] = 0.f;

            const float4* w1q = reinterpret_cast<const float4*>(W1);
            #pragma unroll 4
            for (int i = 0; i < DD; i++) {
                float4 w = __ldg(&w1q[i*64 + q]);
                #pragma unroll
                for (int r = 0; r < 4; r++) {
                    float a = sf[(rg*4 + r)*60 + i];
                    acc[r][0] += a*w.x; acc[r][1] += a*w.y;
                    acc[r][2] += a*w.z; acc[r][3] += a*w.w;
                }
            }
            float4 bb = *reinterpret_cast<const float4*>(&sb1[4*q]);
            #pragma unroll
            for (int r = 0; r < 4; r++) {
                acc[r][0] += bb.x; acc[r][1] += bb.y;
                acc[r][2] += bb.z; acc[r][3] += bb.w;
            }

            // LN over 256 cols: per row, reduce 64 threads = 2 warps
            float s[4], qs[4];
            #pragma unroll
            for (int r = 0; r < 4; r++) {
                s[r]  = acc[r][0] + acc[r][1] + acc[r][2] + acc[r][3];
                qs[r] = acc[r][0]*acc[r][0] + acc[r][1]*acc[r][1]
                      + acc[r][2]*acc[r][2] + acc[r][3]*acc[r][3];
            }
            #pragma unroll
            for (int off = 16; off; off >>= 1) {
                #pragma unroll
                for (int r = 0; r < 4; r++) {
                    s[r]  += __shfl_xor_sync(0xffffffffu, s[r],  off);
                    qs[r] += __shfl_xor_sync(0xffffffffu, qs[r], off);
                }
            }
            if (lane == 0) {
                #pragma unroll
                for (int r = 0; r < 4; r++) {
                    sred[wid*8 + r]     = s[r];
                    sred[wid*8 + 4 + r] = qs[r];
                }
            }
            __syncthreads();

            float4 gg = *reinterpret_cast<const float4*>(&sg1[4*q]);
            float4 be = *reinterpret_cast<const float4*>(&sbe1[4*q]);
            #pragma unroll
            for (int r = 0; r < 4; r++) {
                float st = sred[(2*rg)*8 + r]     + sred[(2*rg+1)*8 + r];
                float qt = sred[(2*rg)*8 + 4 + r] + sred[(2*rg+1)*8 + 4 + r];
                float mu = st * (1.f/256.f);
                float rs = rsqrtf(qt * (1.f/256.f) - mu*mu + LNEPS);
                float4 hv;
                hv.x = fmaxf((acc[r][0]-mu)*rs*gg.x + be.x, 0.f);
                hv.y = fmaxf((acc[r][1]-mu)*rs*gg.y + be.y, 0.f);
                hv.z = fmaxf((acc[r][2]-mu)*rs*gg.z + be.z, 0.f);
                hv.w = fmaxf((acc[r][3]-mu)*rs*gg.w + be.w, 0.f);
                *reinterpret_cast<float4*>(&sh1[(rg*4 + r)*HH1 + 4*q]) = hv;
            }
        }
        __syncthreads();

        // ---- layer 2: 256 -> 128. 256 threads, 4 cols x 4 rows per thread ----
        if (tid < 256) {
            const int cq = tid & 31;           // cols 4cq..4cq+3
            const int rg = tid >> 5;           // 8 rowgroups x 4 rows (= wid, whole warp same rows)
            float acc[4][4];
            #pragma unroll
            for (int r = 0; r < 4; r++)
                #pragma unroll
                for (int c = 0; c < 4; c++) acc[r][c] = 0.f;

            const float4* w2q = reinterpret_cast<const float4*>(W2);
            #pragma unroll 4
            for (int i = 0; i < HH1; i++) {
                float4 w = __ldg(&w2q[i*32 + cq]);
                #pragma unroll
                for (int r = 0; r < 4; r++) {
                    float a = sh1[(rg*4 + r)*HH1 + i];
                    acc[r][0] += a*w.x; acc[r][1] += a*w.y;
                    acc[r][2] += a*w.z; acc[r][3] += a*w.w;
                }
            }
            float4 bb = *reinterpret_cast<const float4*>(&sb2[4*cq]);
            #pragma unroll
            for (int r = 0; r < 4; r++) {
                acc[r][0] += bb.x; acc[r][1] += bb.y;
                acc[r][2] += bb.z; acc[r][3] += bb.w;
            }

            // LN over 128 cols: whole warp owns these 4 rows -> pure butterfly
            float s[4], qs[4];
            #pragma unroll
            for (int r = 0; r < 4; r++) {
                s[r]  = acc[r][0] + acc[r][1] + acc[r][2] + acc[r][3];
                qs[r] = acc[r][0]*acc[r][0] + acc[r][1]*acc[r][1]
                      + acc[r][2]*acc[r][2] + acc[r][3]*acc[r][3];
            }
            #pragma unroll
            for (int off = 16; off; off >>= 1) {
                #pragma unroll
                for (int r = 0; r < 4; r++) {
                    s[r]  += __shfl_xor_sync(0xffffffffu, s[r],  off);
                    qs[r] += __shfl_xor_sync(0xffffffffu, qs[r], off);
                }
            }
            float4 gg = *reinterpret_cast<const float4*>(&sg2[4*cq]);
            float4 be = *reinterpret_cast<const float4*>(&sbe2[4*cq]);
            #pragma unroll
            for (int r = 0; r < 4; r++) {
                float mu = s[r] * (1.f/128.f);
                float rs = rsqrtf(qs[r] * (1.f/128.f) - mu*mu + LNEPS);
                float4 hv;
                hv.x = fmaxf((acc[r][0]-mu)*rs*gg.x + be.x, 0.f);
                hv.y = fmaxf((acc[r][1]-mu)*rs*gg.y + be.y, 0.f);
                hv.z = fmaxf((acc[r][2]-mu)*rs*gg.z + be.z, 0.f);
                hv.w = fmaxf((acc[r][3]-mu)*rs*gg.w + be.w, 0.f);
                *reinterpret_cast<float4*>(&sh2[(rg*4 + r)*HH2 + 4*cq]) = hv;
            }
        }
        __syncthreads();

        // ---- layer 3 + softmax: 256 threads = 32 rows x 8 outputs ----
        if (tid < RPC*EE) {
            const int r = tid >> 3;
            const int o = tid & 7;
            float a = sb3[o];
            #pragma unroll 8
            for (int i = 0; i < HH2; i++) a += sh2[r*HH2 + i] * sW3[i*EE + o];

            float mx = a;
            #pragma unroll
            for (int off = 4; off; off >>= 1)
                mx = fmaxf(mx, __shfl_xor_sync(0xffffffffu, mx, off));
            float ex = __expf(a - mx);
            float sme = ex;
            #pragma unroll
            for (int off = 4; off; off >>= 1)
                sme += __shfl_xor_sync(0xffffffffu, sme, off);
            const int row = row0 + r;
            lout[(size_t)row*EE + o] = a;
            wout[(size_t)row*EE + o] = ex / sme;
        }
        __syncthreads();
    }
}

// ---------------------------------------------------------------------------
extern "C" void kernel_launch(void* const* d_in, const int* in_sizes, int n_in,
                              void* d_out, int out_size)
{
    (void)in_sizes; (void)n_in; (void)out_size;
    const float* P   = (const float*)d_in[0];
    const float* W1  = (const float*)d_in[1];
    const float* b1  = (const float*)d_in[2];
    const float* g1  = (const float*)d_in[3];
    const float* be1 = (const float*)d_in[4];
    const float* W2  = (const float*)d_in[5];
    const float* b2  = (const float*)d_in[6];
    const float* g2  = (const float*)d_in[7];
    const float* be2 = (const float*)d_in[8];
    const float* W3  = (const float*)d_in[9];
    const float* b3  = (const float*)d_in[10];

    float* out   = (float*)d_out;
    float* wout  = out;                    // weights: B*8
    float* lout  = out + (size_t)BB*EE;    // logits:  B*8
    float* feats = out + (size_t)2*BB*EE;  // feats:   B*59

    const size_t smemA = (size_t)(EE*CC + 2*8*256) * sizeof(float);  // 48384 B
    cudaFuncSetAttribute(feat_kernel, cudaFuncAttributeMaxDynamicSharedMemorySize, (int)smemA);
    feat_kernel<<<592, 256, smemA>>>(P, feats);

    const size_t smemB = (size_t)(RPC*60 + RPC*HH1 + RPC*HH2 + HH2*EE
                                  + 3*HH1 + 3*HH2 + EE + 128) * sizeof(float);  // ~66KB
    cudaFuncSetAttribute(mlp_kernel, cudaFuncAttributeMaxDynamicSharedMemorySize, (int)smemB);
    mlp_kernel<<<296, 512, smemB>>>(feats, W1, b1, g1, be1, W2, b2, g2, be2, W3, b3,
                                    wout, lout);
}